// round 13
// baseline (speedup 1.0000x reference)
#include <cuda_runtime.h>
#include <cuda_fp16.h>
#include <cstdint>
#include <cstddef>

#define Bb 512
#define Tt 512
#define Ff 128
#define Uu 256
#define G4 1024   // 4*U

// ---------------- device scratch ----------------
__device__ float g_xz[(size_t)Bb * Tt * G4];          // precomputed x@kernel+bias

// ---------------- helpers ----------------
__device__ __forceinline__ void mma_f16(float& d0, float& d1, float& d2, float& d3,
                                        unsigned a0, unsigned a1, unsigned a2, unsigned a3,
                                        unsigned b0, unsigned b1) {
    asm volatile("mma.sync.aligned.m16n8k16.row.col.f32.f16.f16.f32 "
                 "{%0,%1,%2,%3}, {%4,%5,%6,%7}, {%8,%9}, {%0,%1,%2,%3};"
                 : "+f"(d0), "+f"(d1), "+f"(d2), "+f"(d3)
                 : "r"(a0), "r"(a1), "r"(a2), "r"(a3), "r"(b0), "r"(b1));
}
__device__ __forceinline__ unsigned pk2(__half x, __half y) {
    __half2 t; t.x = x; t.y = y;
    return *reinterpret_cast<unsigned*>(&t);
}
__device__ __forceinline__ void cp_async16(void* sdst, const void* gsrc) {
    unsigned sa = (unsigned)__cvta_generic_to_shared(sdst);
    asm volatile("cp.async.cg.shared.global [%0], [%1], 16;" :: "r"(sa), "l"(gsrc));
}
__device__ __forceinline__ void ldsm4(unsigned& r0, unsigned& r1, unsigned& r2, unsigned& r3,
                                      const void* p) {
    unsigned sa = (unsigned)__cvta_generic_to_shared(p);
    asm volatile("ldmatrix.sync.aligned.m8n8.x4.shared.b16 {%0,%1,%2,%3}, [%4];"
                 : "=r"(r0), "=r"(r1), "=r"(r2), "=r"(r3) : "r"(sa));
}

// ================= Phase 1: XZ = x @ kernel + bias (fp16 1-pass mma) =================
// CTA tile 128M x 64N, K=128. 512 threads = 16 warps (4x4), warp tile 32x16.
#define P1_STR 136

__global__ __launch_bounds__(512, 2) void xz_gemm(const float* __restrict__ x,
                                                  const float* __restrict__ wk,
                                                  const float* __restrict__ bias) {
    extern __shared__ char smc[];
    __half* Ax  = (__half*)smc;                        // [128][136]
    __half* Bx  = (__half*)(smc + 34816);              // [64 n][136 k]

    int tid  = threadIdx.x;
    int nblk = blockIdx.x, mblk = blockIdx.y;
    const float* xblk = x + (size_t)mblk * 128 * Ff;
    const float* wcol = wk + (size_t)nblk * 64;

    // A fill: x tile [128][128] fp32 -> fp16
    {
        int r = tid >> 2, q = tid & 3;
        const float* xr = xblk + (size_t)r * Ff;
#pragma unroll
        for (int jj = 0; jj < 8; jj++) {
            int col = 4 * q + 16 * jj;
            float4 v = *(const float4*)(xr + col);
            *(unsigned*)(Ax + r * P1_STR + col)     = pk2(__float2half_rn(v.x), __float2half_rn(v.y));
            *(unsigned*)(Ax + r * P1_STR + col + 2) = pk2(__float2half_rn(v.z), __float2half_rn(v.w));
        }
    }
    // B fill: Bs[n][k] = wk[k][nblk*64+n] -> fp16
#pragma unroll
    for (int i = 0; i < 16; i++) {
        int flat = tid + 512 * i;
        int k = flat >> 6, n = flat & 63;
        Bx[n * P1_STR + k] = __float2half_rn(wcol[(size_t)k * G4 + n]);
    }
    __syncthreads();

    int w = tid >> 5, lane = tid & 31;
    int wm = w >> 2, wn = w & 3;
    int g = lane >> 2, tq = lane & 3;
    int mb = 32 * wm, nb = 16 * wn;

    float acc[2][2][4];
#pragma unroll
    for (int ni = 0; ni < 2; ni++) {
        float2 bv = *(const float2*)(bias + nblk * 64 + nb + 8 * ni + 2 * tq);
#pragma unroll
        for (int mi = 0; mi < 2; mi++) {
            acc[mi][ni][0] = bv.x; acc[mi][ni][1] = bv.y;
            acc[mi][ni][2] = bv.x; acc[mi][ni][3] = bv.y;
        }
    }

#pragma unroll 4
    for (int kc = 0; kc < 128; kc += 16) {
        unsigned bh[2][2];
#pragma unroll
        for (int ni = 0; ni < 2; ni++) {
            const __half* bp = Bx + (nb + 8 * ni + g) * P1_STR + kc + 2 * tq;
            bh[ni][0] = *(const unsigned*)bp;
            bh[ni][1] = *(const unsigned*)(bp + 8);
        }
#pragma unroll
        for (int mi = 0; mi < 2; mi++) {
            const __half* ap = Ax + (mb + 16 * mi + g) * P1_STR + kc + 2 * tq;
            unsigned a0 = *(const unsigned*)ap;
            unsigned a1 = *(const unsigned*)(ap + 8 * P1_STR);
            unsigned a2 = *(const unsigned*)(ap + 8);
            unsigned a3 = *(const unsigned*)(ap + 8 * P1_STR + 8);
#pragma unroll
            for (int ni = 0; ni < 2; ni++)
                mma_f16(acc[mi][ni][0], acc[mi][ni][1], acc[mi][ni][2], acc[mi][ni][3],
                        a0, a1, a2, a3, bh[ni][0], bh[ni][1]);
        }
    }

    float* od = g_xz + ((size_t)mblk * 128) * G4 + nblk * 64;
#pragma unroll
    for (int mi = 0; mi < 2; mi++) {
#pragma unroll
        for (int ni = 0; ni < 2; ni++) {
            int row = mb + 16 * mi + g, col = nb + 8 * ni + 2 * tq;
            *(float2*)(od + (size_t)row * G4 + col)       = make_float2(acc[mi][ni][0], acc[mi][ni][1]);
            *(float2*)(od + (size_t)(row + 8) * G4 + col) = make_float2(acc[mi][ni][2], acc[mi][ni][3]);
        }
    }
}

// ================= Phase 2: persistent recurrence (fp16 mma + cluster DSMEM) ======
// 128 CTAs = 16 clusters of 8. Cluster = one batch-group (32 batches); CTA rank cg
// owns units [32cg, 32cg+32) -> 128 gate-cols. h exchanged via DSMEM stores into
// all 8 peers' double-buffered SMEM A tiles; cluster.sync per step. No global h.
#define WS 264     // W smem stride (fp16 elements)
#define AS 264     // A(h) smem stride
#define AH_OFF 67584
#define AH_BUF 16896           // bytes per Ah buffer (32*264*2)
#define XS_OFF 101376
#define XSS 132    // xz smem stride (floats)
#define XSBUF (32 * XSS)
#define ZS_OFF 135168
#define ZSS 136    // z smem stride (floats)
#define RC_SMEM 152576

__global__ void __cluster_dims__(8, 1, 1) __launch_bounds__(256, 1)
lstm_rec(const float* __restrict__ rk,
         const float* __restrict__ dw,
         const float* __restrict__ db,
         float* __restrict__ out) {
    extern __shared__ char smc[];
    __half* Wh = (__half*)smc;                          // [128][264]
    __half* Ah = (__half*)(smc + AH_OFF);               // [2][32][264]
    float* xs = (float*)(smc + XS_OFF);                 // [2][32][132]
    float* zs = (float*)(smc + ZS_OFF);                 // [32][136]
    uint32_t sb = (uint32_t)__cvta_generic_to_shared(smc);

    int tid = threadIdx.x;
    uint32_t cg;
    asm("mov.u32 %0, %%cluster_ctarank;" : "=r"(cg));
    int bg    = blockIdx.x >> 3;
    int bbase = bg * 32;
    int ubase = (int)cg * 32;

    // one-time: weight slice -> fp16, layout Wh[j][k], j = gate*32 + u
    for (int i = tid; i < 128 * 256; i += 256) {
        int j = i >> 8, k = i & 255;
        int gate = j >> 5, u = j & 31;
        Wh[j * WS + k] = __float2half_rn(rk[(size_t)k * G4 + gate * Uu + ubase + u]);
    }
    // zero both Ah buffers (h0 = 0)
    for (int i = tid; i < 2 * 32 * AS / 2; i += 256)
        ((uint32_t*)Ah)[i] = 0u;

    int w = tid >> 5, lane = tid & 31;
    int g = lane >> 2, tq = lane & 3;
    int nb = 16 * w;                 // warp covers local cols [16w,16w+16)
    int gb = tid >> 3;               // gate-layer batch
    int gu = (tid & 7) * 4;          // gate-layer unit base (within this CTA's 32)
    float cst[4] = {0.f, 0.f, 0.f, 0.f};

    // t-invariant ldmatrix lane-address components
    int aRow = lane & 15;
    int aK   = (lane >> 4) * 8;
    int bRow = nb + 8 * (lane >> 4) + (lane & 7);
    int bK   = 8 * ((lane >> 3) & 1);

    // DSMEM store base (byte offset within Ah, same in every CTA)
    uint32_t ah_store_la = sb + AH_OFF + (uint32_t)(gb * (AS * 2) + (ubase + gu) * 2);

    // prefetch xz tile for t=0 into xs buf 0
#pragma unroll
    for (int i = 0; i < 4; i++) {
        int flat4 = tid + 256 * i;
        int bbq = flat4 >> 5, rest = flat4 & 31, gg = rest >> 3, u4 = rest & 7;
        const float* gsrc = g_xz + ((size_t)(bbase + bbq) * Tt + 0) * G4 + gg * Uu + ubase + 4 * u4;
        cp_async16(xs + bbq * XSS + gg * 32 + 4 * u4, gsrc);
    }
    asm volatile("cp.async.commit_group;" ::: "memory");
    __syncthreads();
    // all CTAs' Wh/Ah ready before any peer stores arrive
    asm volatile("barrier.cluster.arrive.aligned;" ::: "memory");
    asm volatile("barrier.cluster.wait.aligned;" ::: "memory");

    for (int t = 0; t < Tt; t++) {
        int cur = t & 1, nxt = cur ^ 1;

        asm volatile("cp.async.wait_group 0;" ::: "memory");
        __syncthreads();   // xs[cur] visible to all threads

        // acc init from xz tile
        float acc[2][2][4];
#pragma unroll
        for (int mi = 0; mi < 2; mi++) {
#pragma unroll
            for (int ni = 0; ni < 2; ni++) {
                const float* zp = xs + cur * XSBUF + (16 * mi + g) * XSS + nb + 8 * ni + 2 * tq;
                float2 a = *(const float2*)zp;
                float2 b = *(const float2*)(zp + 8 * XSS);
                acc[mi][ni][0] = a.x; acc[mi][ni][1] = a.y;
                acc[mi][ni][2] = b.x; acc[mi][ni][3] = b.y;
            }
        }

        // prefetch xz(t+1) early: overlaps K-loop + gates + cluster.sync
        if (t + 1 < Tt) {
#pragma unroll
            for (int i = 0; i < 4; i++) {
                int flat4 = tid + 256 * i;
                int bbq = flat4 >> 5, rest = flat4 & 31, gg = rest >> 3, u4 = rest & 7;
                const float* gsrc = g_xz + ((size_t)(bbase + bbq) * Tt + (t + 1)) * G4 + gg * Uu + ubase + 4 * u4;
                cp_async16(xs + nxt * XSBUF + bbq * XSS + gg * 32 + 4 * u4, gsrc);
            }
            asm volatile("cp.async.commit_group;" ::: "memory");
        }

        // K loop: z += h @ Wr (fp16, ldmatrix fragments from Ah[cur])
        const __half* AhC = (const __half*)((char*)Ah + cur * AH_BUF);
#pragma unroll 4
        for (int kc = 0; kc < 256; kc += 16) {
            unsigned bh0, bh1, bh2, bh3;
            ldsm4(bh0, bh1, bh2, bh3, Wh + bRow * WS + kc + bK);
#pragma unroll
            for (int mi = 0; mi < 2; mi++) {
                unsigned a0, a1, a2, a3;
                ldsm4(a0, a1, a2, a3, AhC + (16 * mi + aRow) * AS + kc + aK);
                mma_f16(acc[mi][0][0], acc[mi][0][1], acc[mi][0][2], acc[mi][0][3],
                        a0, a1, a2, a3, bh0, bh1);
                mma_f16(acc[mi][1][0], acc[mi][1][1], acc[mi][1][2], acc[mi][1][3],
                        a0, a1, a2, a3, bh2, bh3);
            }
        }

        // bounce z through SMEM (decouple gate layout from mma fragments)
#pragma unroll
        for (int mi = 0; mi < 2; mi++) {
#pragma unroll
            for (int ni = 0; ni < 2; ni++) {
                float* zp = zs + (16 * mi + g) * ZSS + nb + 8 * ni + 2 * tq;
                *(float2*)zp             = make_float2(acc[mi][ni][0], acc[mi][ni][1]);
                *(float2*)(zp + 8 * ZSS) = make_float2(acc[mi][ni][2], acc[mi][ni][3]);
            }
        }
        __syncthreads();

        // gate layer: thread -> (batch gb, units gu..gu+3); DSMEM-broadcast h
        {
            const float* zr = zs + gb * ZSS + gu;
            float4 zi = *(const float4*)(zr + 0);
            float4 zf = *(const float4*)(zr + 32);
            float4 zg = *(const float4*)(zr + 64);
            float4 zo = *(const float4*)(zr + 96);
            float zia[4] = {zi.x, zi.y, zi.z, zi.w};
            float zfa[4] = {zf.x, zf.y, zf.z, zf.w};
            float zga[4] = {zg.x, zg.y, zg.z, zg.w};
            float zoa[4] = {zo.x, zo.y, zo.z, zo.w};
            __half hn4[4];
#pragma unroll
            for (int e = 0; e < 4; e++) {
                float ig = 1.f / (1.f + __expf(-zia[e]));
                float fg = 1.f / (1.f + __expf(-zfa[e]));
                float gg = fmaxf(zga[e], 0.f);
                float og = 1.f / (1.f + __expf(-zoa[e]));
                float cn = fg * cst[e] + ig * gg;
                cst[e] = cn;
                hn4[e] = __float2half_rn(og * fmaxf(cn, 0.f));
            }
            unsigned lo = pk2(hn4[0], hn4[1]);
            unsigned hi = pk2(hn4[2], hn4[3]);
            unsigned long long v64 = ((unsigned long long)hi << 32) | lo;
            uint32_t la = ah_store_la + (uint32_t)(nxt * AH_BUF);
#pragma unroll
            for (int r = 0; r < 8; r++) {
                uint32_t ra;
                asm("mapa.shared::cluster.u32 %0, %1, %2;" : "=r"(ra) : "r"(la), "r"(r));
                asm volatile("st.shared::cluster.b64 [%0], %1;" :: "r"(ra), "l"(v64));
            }
        }

        // cluster barrier: my Ah[cur] reads done; my stores to peers' Ah[nxt] visible
        asm volatile("barrier.cluster.arrive.aligned;" ::: "memory");
        asm volatile("barrier.cluster.wait.aligned;" ::: "memory");
    }

    // final dense: out[b] = h_T[b,:] . dw + db   (T even -> final h in Ah[0], local)
    if (cg == 0) {
        int b = tid >> 3, r = tid & 7;
        const __half* hv = Ah + b * AS;   // Ah buffer 0, row b (full 256 units)
        float s = 0.f;
#pragma unroll
        for (int j = 0; j < 32; j++) {
            int u = r + 8 * j;
            s += __half2float(hv[u]) * dw[u];
        }
        s += __shfl_down_sync(0xffffffffu, s, 4);
        s += __shfl_down_sync(0xffffffffu, s, 2);
        s += __shfl_down_sync(0xffffffffu, s, 1);
        if (r == 0) out[bbase + b] = s + db[0];
    }
}

// ---------------- launch ----------------
extern "C" void kernel_launch(void* const* d_in, const int* in_sizes, int n_in,
                              void* d_out, int out_size) {
    const float* x    = (const float*)d_in[0];
    const float* wk   = (const float*)d_in[1];
    const float* rk   = (const float*)d_in[2];
    const float* bias = (const float*)d_in[3];
    const float* dw   = (const float*)d_in[4];
    const float* db   = (const float*)d_in[5];
    float* out = (float*)d_out;

    const int smem1 = 52224;    // phase-1: A [128][136] + B [64][136] fp16
    cudaFuncSetAttribute(xz_gemm,  cudaFuncAttributeMaxDynamicSharedMemorySize, smem1);
    cudaFuncSetAttribute(lstm_rec, cudaFuncAttributeMaxDynamicSharedMemorySize, RC_SMEM);

    xz_gemm<<<dim3(G4 / 64, (Bb * Tt) / 128), 512, smem1>>>(x, wk, bias);
    lstm_rec<<<128, 256, RC_SMEM>>>(rk, dw, db, out);
}